// round 14
// baseline (speedup 1.0000x reference)
#include <cuda_runtime.h>
#include <cuda_bf16.h>
#include <cuda_fp16.h>
#include <cstdint>

#define Bb 4
#define Ls 2048
#define Dd 1024
#define Hh 16
#define DKk 64
#define Mrows 8192
#define SZ ((size_t)Bb*Hh*Ls*DKk)   // 8,388,608 elements per Q/K/V slab

// ---------------- scratch (__device__ globals; allocation-free rule) -------
__device__ __nv_bfloat16 g_Xh[3*Mrows*Dd];   // split q,k,v inputs (slab z)
__device__ __nv_bfloat16 g_Xl[3*Mrows*Dd];
__device__ __nv_bfloat16 g_Wh[4*Dd*Dd];      // split wq,wk,wv,wo (slab z)
__device__ __nv_bfloat16 g_Wl[4*Dd*Dd];
// Q,K slabs hold bf16 hi/lo; V slab (z=2) holds fp16 hi/lo (raw 16-bit lanes)
__device__ __nv_bfloat16 g_Ph[3*Bb*Hh*Ls*DKk];
__device__ __nv_bfloat16 g_Pl[3*Bb*Hh*Ls*DKk];
__device__ __nv_bfloat16 g_Oh[Mrows*Dd];     // attn out hi/lo, row-major [M,D]
__device__ __nv_bfloat16 g_Ol[Mrows*Dd];

// ---------------- PTX helpers (family-portable; no tcgen05) ----------------
__device__ __forceinline__ uint32_t s2u(const void* p) {
    uint32_t a;
    asm("{ .reg .u64 t; cvta.to.shared.u64 t, %1; cvt.u32.u64 %0, t; }"
        : "=r"(a) : "l"(p));
    return a;
}
__device__ __forceinline__ void cp16(uint32_t dst, const void* src) {
    asm volatile("cp.async.cg.shared.global [%0], [%1], 16;" :: "r"(dst), "l"(src));
}
__device__ __forceinline__ void ldsm4(uint32_t addr, uint32_t& r0, uint32_t& r1,
                                      uint32_t& r2, uint32_t& r3) {
    asm volatile("ldmatrix.sync.aligned.m8n8.x4.shared.b16 {%0,%1,%2,%3}, [%4];"
                 : "=r"(r0), "=r"(r1), "=r"(r2), "=r"(r3) : "r"(addr));
}
__device__ __forceinline__ void ldsm4t(uint32_t addr, uint32_t& r0, uint32_t& r1,
                                       uint32_t& r2, uint32_t& r3) {
    asm volatile("ldmatrix.sync.aligned.m8n8.x4.trans.shared.b16 {%0,%1,%2,%3}, [%4];"
                 : "=r"(r0), "=r"(r1), "=r"(r2), "=r"(r3) : "r"(addr));
}
__device__ __forceinline__ void mma16816(float* c, const uint32_t* a,
                                         uint32_t b0, uint32_t b1) {
    asm volatile(
        "mma.sync.aligned.m16n8k16.row.col.f32.bf16.bf16.f32 "
        "{%0,%1,%2,%3}, {%4,%5,%6,%7}, {%8,%9}, {%0,%1,%2,%3};"
        : "+f"(c[0]), "+f"(c[1]), "+f"(c[2]), "+f"(c[3])
        : "r"(a[0]), "r"(a[1]), "r"(a[2]), "r"(a[3]), "r"(b0), "r"(b1));
}
__device__ __forceinline__ void mma16816h(float* c, const uint32_t* a,
                                          uint32_t b0, uint32_t b1) {
    asm volatile(
        "mma.sync.aligned.m16n8k16.row.col.f32.f16.f16.f32 "
        "{%0,%1,%2,%3}, {%4,%5,%6,%7}, {%8,%9}, {%0,%1,%2,%3};"
        : "+f"(c[0]), "+f"(c[1]), "+f"(c[2]), "+f"(c[3])
        : "r"(a[0]), "r"(a[1]), "r"(a[2]), "r"(a[3]), "r"(b0), "r"(b1));
}
__device__ __forceinline__ uint32_t swz(uint32_t off) {
    return off ^ ((off >> 3) & 0x70);
}
__device__ __forceinline__ uint32_t cvt_bf16x2(float h, float l) {
    uint32_t r;
    asm("cvt.rn.bf16x2.f32 %0, %1, %2;" : "=r"(r) : "f"(h), "f"(l));
    return r;
}
// pack two fp32 into f16x2: {hi_lane=h, lo_lane=l}
__device__ __forceinline__ uint32_t cvt_f16x2(float h, float l) {
    uint32_t r;
    asm("cvt.rn.f16x2.f32 %0, %1, %2;" : "=r"(r) : "f"(h), "f"(l));
    return r;
}
// truncation split: hi = x with low 16 mantissa bits zeroed (exact in fp32)
__device__ __forceinline__ uint32_t trunc_bits(float x) {
    return __float_as_uint(x) & 0xffff0000u;
}

// ---------------- batched split kernels: fp32 -> (hi, lo) bf16 --------------
__device__ __forceinline__ void split_store(const float* x, __nv_bfloat16* hi,
                                            __nv_bfloat16* lo, size_t slot)
{
    float4 v = ((const float4*)x)[0];
    float f[4] = {v.x, v.y, v.z, v.w};
    uint32_t ub[4];
    #pragma unroll
    for (int j = 0; j < 4; j++) ub[j] = trunc_bits(f[j]);
    ((uint32_t*)hi)[2*slot]   = __byte_perm(ub[0], ub[1], 0x7632);
    ((uint32_t*)hi)[2*slot+1] = __byte_perm(ub[2], ub[3], 0x7632);
    ((uint32_t*)lo)[2*slot]   = cvt_bf16x2(f[1] - __uint_as_float(ub[1]),
                                           f[0] - __uint_as_float(ub[0]));
    ((uint32_t*)lo)[2*slot+1] = cvt_bf16x2(f[3] - __uint_as_float(ub[3]),
                                           f[2] - __uint_as_float(ub[2]));
}

__global__ __launch_bounds__(256) void split3_kernel(
    const float* __restrict__ x0, const float* __restrict__ x1,
    const float* __restrict__ x2,
    __nv_bfloat16* __restrict__ hi, __nv_bfloat16* __restrict__ lo, int n4)
{
    int i = blockIdx.x * 256 + threadIdx.x;
    if (i >= n4) return;
    int z = blockIdx.y;
    const float* x = (z == 0) ? x0 : (z == 1) ? x1 : x2;
    size_t slot = (size_t)z * n4 + i;
    split_store(x + 4*(size_t)i, hi, lo, slot);
}

__global__ __launch_bounds__(256) void split4_kernel(
    const float* __restrict__ x0, const float* __restrict__ x1,
    const float* __restrict__ x2, const float* __restrict__ x3,
    __nv_bfloat16* __restrict__ hi, __nv_bfloat16* __restrict__ lo, int n4)
{
    int i = blockIdx.x * 256 + threadIdx.x;
    if (i >= n4) return;
    int z = blockIdx.y;
    const float* x = (z == 0) ? x0 : (z == 1) ? x1 : (z == 2) ? x2 : x3;
    size_t slot = (size_t)z * n4 + i;
    split_store(x + 4*(size_t)i, hi, lo, slot);
}

// ---------------- persistent mma.sync bf16x3 GEMM ---------------------------
// Grid-stride over tiles (512 tiles per z-slab: 64 m-blocks x 8 n-blocks).
// scatter=1: bf16 hi/lo out (z<2) or fp16 hi/lo out (z==2, for fp16 PV);
// scatter=0: fp32 row-major out with bias.
#define GEMM_SMEM 98304   // 3 stages x (A 16KB + B 16KB)

__global__ __launch_bounds__(128) void gemm_mma(
    const __nv_bfloat16* __restrict__ AhB, const __nv_bfloat16* __restrict__ AlB,
    const __nv_bfloat16* __restrict__ WhB, const __nv_bfloat16* __restrict__ WlB,
    const float* __restrict__ b0p, const float* __restrict__ b1p,
    const float* __restrict__ b2p,
    float* __restrict__ C,
    __nv_bfloat16* __restrict__ ChB, __nv_bfloat16* __restrict__ ClB,
    int scatter, int zbase, int ntiles)
{
    extern __shared__ char smem[];
    const uint32_t sb = s2u(smem);
    const int tid = threadIdx.x, wid = tid >> 5, lane = tid & 31;
    const int warp_m = wid & 1, warp_n = wid >> 1;

    const int arow = lane & 15;
    const int akp  = (lane >> 4) & 1;
    const int brow = (lane & 7) + ((lane >> 4) << 3);
    const int bkp  = (lane >> 3) & 1;

    for (int t = blockIdx.x; t < ntiles; t += gridDim.x) {
        const int z = zbase + (t >> 9);
        const int rem = t & 511;
        const int bm = (rem >> 3) * 128, bn = (rem & 7) * 128;
        const int za = scatter ? z : 0;

        const __nv_bfloat16* Ah = AhB + (size_t)za * Mrows * Dd;
        const __nv_bfloat16* Al = AlB + (size_t)za * Mrows * Dd;
        const __nv_bfloat16* Wh = WhB + (size_t)z * Dd * Dd;
        const __nv_bfloat16* Wl = WlB + (size_t)z * Dd * Dd;
        const float* bias = (z == 1) ? b1p : (z == 2) ? b2p : b0p;
        __nv_bfloat16* Ch = ChB + (size_t)z * SZ;
        __nv_bfloat16* Cl = ClB + (size_t)z * SZ;
        const bool vf16 = scatter && (z == 2);

        float acc[4][8][4] = {};

        auto stage = [&](int c, int buf) {
            const __nv_bfloat16* As = (c >= 16 && c < 32) ? Al : Ah;
            const __nv_bfloat16* Ws = (c < 32) ? Wh : Wl;
            const int koff = (c & 15) << 6;
            const uint32_t abase = sb + buf * 32768;
            const uint32_t bbase = abase + 16384;
            #pragma unroll
            for (int u = 0; u < 8; u++) {
                int i = tid + u * 128;
                int row = i >> 3, seg = i & 7;
                uint32_t off = row * 128 + seg * 16;
                cp16(abase + swz(off), As + (size_t)(bm + row) * Dd + koff + seg * 8);
            }
            #pragma unroll
            for (int u = 0; u < 8; u++) {
                int i = tid + u * 128;
                int row = i >> 3, seg = i & 7;
                uint32_t off = row * 128 + seg * 16;
                cp16(bbase + swz(off), Ws + (size_t)(bn + row) * Dd + koff + seg * 8);
            }
            asm volatile("cp.async.commit_group;" ::: "memory");
        };

        stage(0, 0);
        stage(1, 1);
        for (int c = 0; c < 48; c++) {
            if (c < 46) {
                asm volatile("cp.async.wait_group 1;" ::: "memory");
            } else {
                asm volatile("cp.async.wait_group 0;" ::: "memory");
            }
            __syncthreads();
            if (c + 2 < 48) stage(c + 2, (c + 2) % 3);

            const uint32_t abase = sb + (c % 3) * 32768;
            const uint32_t bbase = abase + 16384;
            #pragma unroll
            for (int ks = 0; ks < 4; ks++) {
                uint32_t a[4][4];
                #pragma unroll
                for (int mt = 0; mt < 4; mt++) {
                    int r = warp_m * 64 + mt * 16 + arow;
                    ldsm4(abase + swz(r * 128 + ks * 32 + akp * 16),
                          a[mt][0], a[mt][1], a[mt][2], a[mt][3]);
                }
                uint32_t b[4][4];
                #pragma unroll
                for (int nt2 = 0; nt2 < 4; nt2++) {
                    int r = warp_n * 64 + nt2 * 16 + brow;
                    ldsm4(bbase + swz(r * 128 + ks * 32 + bkp * 16),
                          b[nt2][0], b[nt2][1], b[nt2][2], b[nt2][3]);
                }
                #pragma unroll
                for (int mt = 0; mt < 4; mt++)
                    #pragma unroll
                    for (int nt2 = 0; nt2 < 4; nt2++) {
                        mma16816(acc[mt][nt2*2],     a[mt], b[nt2][0], b[nt2][1]);
                        mma16816(acc[mt][nt2*2 + 1], a[mt], b[nt2][2], b[nt2][3]);
                    }
            }
        }

        #pragma unroll
        for (int mt = 0; mt < 4; mt++) {
            int row0 = bm + warp_m * 64 + mt * 16 + (lane >> 2);
            #pragma unroll
            for (int nt = 0; nt < 8; nt++) {
                int col = bn + warp_n * 64 + nt * 8 + (lane & 3) * 2;
                float c0 = __ldg(bias + col), c1 = __ldg(bias + col + 1);
                #pragma unroll
                for (int half = 0; half < 2; half++) {
                    int m = row0 + half * 8;
                    float v0 = acc[mt][nt][half*2]     + c0;
                    float v1 = acc[mt][nt][half*2 + 1] + c1;
                    if (scatter) {
                        int b_ = m >> 11, l_ = m & 2047;
                        int h_ = col >> 6, d_ = col & 63;
                        size_t idx = ((size_t)((b_ * Hh + h_) * Ls + l_)) * DKk + d_;
                        if (vf16) {
                            // fp16 hi/lo for V (feeds fp16 PV in attention)
                            __half h0 = __float2half_rn(v0);
                            __half h1 = __float2half_rn(v1);
                            float l0 = v0 - __half2float(h0);
                            float l1 = v1 - __half2float(h1);
                            *(uint32_t*)(Ch + idx) =
                                ((uint32_t)__half_as_ushort(h1) << 16) |
                                __half_as_ushort(h0);
                            *(uint32_t*)(Cl + idx) = cvt_f16x2(l1, l0);
                        } else {
                            uint32_t u0 = trunc_bits(v0), u1 = trunc_bits(v1);
                            *(uint32_t*)(Ch + idx) = __byte_perm(u0, u1, 0x7632);
                            *(uint32_t*)(Cl + idx) =
                                cvt_bf16x2(v1 - __uint_as_float(u1),
                                           v0 - __uint_as_float(u0));
                        }
                    } else {
                        float2 v; v.x = v0; v.y = v1;
                        *(float2*)(C + (size_t)m * Dd + col) = v;
                    }
                }
            }
        }
    }
}

// ---------------- tensor-core flash attention -------------------------------
// CTA: 64 queries x one (b,h). 4 warps x 16 rows. 3 CTAs/SM.
// S = QK^T in bf16x3; P converted to fp16 (RNE); PV = 2 fp16 passes
// (P*Vh + P*Vl, V stored as fp16 hi/lo by the projection epilogue).
#define ATTN_SMEM 65536
#define C8 0.18033688011112042f   // 0.125 * log2(e)

__global__ __launch_bounds__(128, 3) void attn_mma()
{
    extern __shared__ char smem[];
    const uint32_t sb = s2u(smem);
    const int tid = threadIdx.x, wid = tid >> 5, lane = tid & 31;
    const int qt = (int)gridDim.x - 1 - (int)blockIdx.x;   // long CTAs first
    const int bh = blockIdx.y;
    const size_t hb = (size_t)bh * Ls * DKk;
    const __nv_bfloat16* Qh_g = g_Ph + hb;
    const __nv_bfloat16* Ql_g = g_Pl + hb;
    const __nv_bfloat16* srcs[4] = {g_Ph + SZ + hb, g_Pl + SZ + hb,
                                    g_Ph + 2*SZ + hb, g_Pl + 2*SZ + hb};

    const int arow = lane & 15;
    const int akp  = (lane >> 4) & 1;
    const int brow = (lane & 7) + ((lane >> 4) << 3);
    const int bkp  = (lane >> 3) & 1;
    const int vrow = (lane & 7) + (((lane >> 3) & 1) << 3);
    const int vdb  = (lane >> 4) * 16;

    // stage Q hi/lo into ring buffer 0 (Kh/Kl slots), then KV tile 0 -> buf 1
    {
        #pragma unroll
        for (int u = 0; u < 4; u++) {
            int i = tid + u * 128;
            int row = i >> 3, seg = i & 7;
            uint32_t off = swz(row * 128 + seg * 16);
            cp16(sb + off,        Qh_g + (size_t)(qt*64 + row) * DKk + seg * 8);
            cp16(sb + 8192 + off, Ql_g + (size_t)(qt*64 + row) * DKk + seg * 8);
        }
        asm volatile("cp.async.commit_group;" ::: "memory");
    }
    auto stage_kv = [&](int kt2, int buf) {
        const uint32_t base = sb + buf * 32768;
        #pragma unroll
        for (int tile = 0; tile < 4; tile++) {
            const __nv_bfloat16* sp = srcs[tile] + (size_t)(kt2 * 64) * DKk;
            uint32_t db = base + tile * 8192;
            #pragma unroll
            for (int u = 0; u < 4; u++) {
                int i = tid + u * 128;
                int row = i >> 3, seg = i & 7;
                cp16(db + swz(row * 128 + seg * 16), sp + row * DKk + seg * 8);
            }
        }
        asm volatile("cp.async.commit_group;" ::: "memory");
    };
    stage_kv(0, 1);

    // Q fragments -> registers (per-thread wait, then CTA-wide sync: cp.async
    // groups are per-thread; ldmatrix reads other threads' staged bytes)
    uint32_t qh[4][4], ql[4][4];
    asm volatile("cp.async.wait_group 1;" ::: "memory");
    __syncthreads();
    #pragma unroll
    for (int ks = 0; ks < 4; ks++) {
        uint32_t off = swz((wid*16 + arow) * 128 + ks * 32 + akp * 16);
        ldsm4(sb + off,        qh[ks][0], qh[ks][1], qh[ks][2], qh[ks][3]);
        ldsm4(sb + 8192 + off, ql[ks][0], ql[ks][1], ql[ks][2], ql[ks][3]);
    }
    __syncthreads();   // all warps done reading Q region; buf0 reusable

    float o[8][4] = {};
    float m_a = -1e30f, m_b = -1e30f, l_a = 0.f, l_b = 0.f;
    const int rA = wid * 16 + (lane >> 2);
    const int cL = (lane & 3) * 2;

    for (int kt = 0; kt <= qt; kt++) {
        const int cur = (kt & 1) ^ 1;          // kt0->buf1, kt1->buf0, ...
        if (kt < qt) {
            stage_kv(kt + 1, cur ^ 1);
            asm volatile("cp.async.wait_group 1;" ::: "memory");
        } else {
            asm volatile("cp.async.wait_group 0;" ::: "memory");
        }
        __syncthreads();

        const uint32_t kb  = sb + cur * 32768;
        const uint32_t klb = kb + 8192;
        const uint32_t vb  = kb + 16384;
        const uint32_t vlb = kb + 24576;

        // ---- S = Q K^T (bf16x3; scale folded into exp2) ----
        float s[8][4] = {};
        #pragma unroll
        for (int ks = 0; ks < 4; ks++) {
            uint32_t bk[4][4];
            #pragma unroll
            for (int p = 0; p < 4; p++)
                ldsm4(kb + swz((p*16 + brow) * 128 + ks * 32 + bkp * 16),
                      bk[p][0], bk[p][1], bk[p][2], bk[p][3]);
            #pragma unroll
            for (int p = 0; p < 4; p++) {
                mma16816(s[2*p],   qh[ks], bk[p][0], bk[p][1]);
                mma16816(s[2*p+1], qh[ks], bk[p][2], bk[p][3]);
                mma16816(s[2*p],   ql[ks], bk[p][0], bk[p][1]);
                mma16816(s[2*p+1], ql[ks], bk[p][2], bk[p][3]);
            }
            #pragma unroll
            for (int p = 0; p < 4; p++) {
                ldsm4(klb + swz((p*16 + brow) * 128 + ks * 32 + bkp * 16),
                      bk[p][0], bk[p][1], bk[p][2], bk[p][3]);
                mma16816(s[2*p],   qh[ks], bk[p][0], bk[p][1]);
                mma16816(s[2*p+1], qh[ks], bk[p][2], bk[p][3]);
            }
        }

        if (kt == qt) {   // causal mask within diagonal tile (raw domain)
            #pragma unroll
            for (int t = 0; t < 8; t++) {
                int c = t * 8 + cL;
                if (c     > rA)     s[t][0] = -1e30f;
                if (c + 1 > rA)     s[t][1] = -1e30f;
                if (c     > rA + 8) s[t][2] = -1e30f;
                if (c + 1 > rA + 8) s[t][3] = -1e30f;
            }
        }

        // ---- online softmax: exp((s-nm)/8) = exp2(fma(s, C8, -nm*C8)) ----
        float tmA = -1e30f, tmB = -1e30f;
        #pragma unroll
        for (int t = 0; t < 8; t++) {
            tmA = fmaxf(tmA, fmaxf(s[t][0], s[t][1]));
            tmB = fmaxf(tmB, fmaxf(s[t][2], s[t][3]));
        }
        tmA = fmaxf(tmA, __shfl_xor_sync(0xffffffffu, tmA, 1));
        tmA = fmaxf(tmA, __shfl_xor_sync(0xffffffffu, tmA, 2));
        tmB = fmaxf(tmB, __shfl_xor_sync(0xffffffffu, tmB, 1));
        tmB = fmaxf(tmB, __shfl_xor_sync(0xffffffffu, tmB, 2));
        float nmA = fmaxf(m_a, tmA), nmB = fmaxf(m_b, tmB);
        float alA = exp2f((m_a - nmA) * C8), alB = exp2f((m_b - nmB) * C8);
        m_a = nmA; m_b = nmB;
        float nAc = nmA * C8, nBc = nmB * C8;

        float psA = 0.f, psB = 0.f;
        #pragma unroll
        for (int t = 0; t < 8; t++) {
            s[t][0] = exp2f(fmaf(s[t][0], C8, -nAc));
            s[t][1] = exp2f(fmaf(s[t][1], C8, -nAc));
            s[t][2] = exp2f(fmaf(s[t][2], C8, -nBc));
            s[t][3] = exp2f(fmaf(s[t][3], C8, -nBc));
            psA += s[t][0] + s[t][1];
            psB += s[t][2] + s[t][3];
        }
        l_a = l_a * alA + psA;
        l_b = l_b * alB + psB;
        #pragma unroll
        for (int t = 0; t < 8; t++) {
            o[t][0] *= alA; o[t][1] *= alA;
            o[t][2] *= alB; o[t][3] *= alB;
        }

        // ---- P -> fp16 A-fragments (single cvt per pair; no hi/lo split) --
        uint32_t ap[4][4];
        #pragma unroll
        for (int kc = 0; kc < 4; kc++) {
            ap[kc][0] = cvt_f16x2(s[2*kc][1],   s[2*kc][0]);
            ap[kc][1] = cvt_f16x2(s[2*kc][3],   s[2*kc][2]);
            ap[kc][2] = cvt_f16x2(s[2*kc+1][1], s[2*kc+1][0]);
            ap[kc][3] = cvt_f16x2(s[2*kc+1][3], s[2*kc+1][2]);
        }

        // ---- O += P V (2 fp16 passes: P*Vh + P*Vl) ----
        #pragma unroll
        for (int kc = 0; kc < 4; kc++) {
            uint32_t bv[4][4];
            #pragma unroll
            for (int p = 0; p < 4; p++)
                ldsm4t(vb + swz((kc*16 + vrow) * 128 + p * 32 + vdb),
                       bv[p][0], bv[p][1], bv[p][2], bv[p][3]);
            #pragma unroll
            for (int p = 0; p < 4; p++) {
                mma16816h(o[2*p],   ap[kc], bv[p][0], bv[p][1]);
                mma16816h(o[2*p+1], ap[kc], bv[p][2], bv[p][3]);
            }
            #pragma unroll
            for (int p = 0; p < 4; p++) {
                ldsm4t(vlb + swz((kc*16 + vrow) * 128 + p * 32 + vdb),
                       bv[p][0], bv[p][1], bv[p][2], bv[p][3]);
                mma16816h(o[2*p],   ap[kc], bv[p][0], bv[p][1]);
                mma16816h(o[2*p+1], ap[kc], bv[p][2], bv[p][3]);
            }
        }
        __syncthreads();
    }

    l_a += __shfl_xor_sync(0xffffffffu, l_a, 1);
    l_a += __shfl_xor_sync(0xffffffffu, l_a, 2);
    l_b += __shfl_xor_sync(0xffffffffu, l_b, 1);
    l_b += __shfl_xor_sync(0xffffffffu, l_b, 2);
    float invA = 1.f / l_a, invB = 1.f / l_b;
    const int b_ = bh >> 4, h_ = bh & 15;
    const int rowA = qt * 64 + rA;
    #pragma unroll
    for (int t = 0; t < 8; t++) {
        int d0 = h_ * 64 + t * 8 + cL;
        float a0 = o[t][0] * invA, a1 = o[t][1] * invA;
        float b0 = o[t][2] * invB, b1 = o[t][3] * invB;
        size_t iA = ((size_t)(b_ * Ls + rowA))     * Dd + d0;
        size_t iB = ((size_t)(b_ * Ls + rowA + 8)) * Dd + d0;
        uint32_t ua0 = trunc_bits(a0), ua1 = trunc_bits(a1);
        uint32_t ub0 = trunc_bits(b0), ub1 = trunc_bits(b1);
        *(uint32_t*)(g_Oh + iA) = __byte_perm(ua0, ua1, 0x7632);
        *(uint32_t*)(g_Ol + iA) = cvt_bf16x2(a1 - __uint_as_float(ua1),
                                             a0 - __uint_as_float(ua0));
        *(uint32_t*)(g_Oh + iB) = __byte_perm(ub0, ub1, 0x7632);
        *(uint32_t*)(g_Ol + iB) = cvt_bf16x2(b1 - __uint_as_float(ub1),
                                             b0 - __uint_as_float(ub0));
    }
}

// ---------------- launch -----------------------------------------------------
extern "C" void kernel_launch(void* const* d_in, const int* in_sizes, int n_in,
                              void* d_out, int out_size)
{
    const float* q    = (const float*)d_in[0];
    const float* k    = (const float*)d_in[1];
    const float* v    = (const float*)d_in[2];
    const float* wq_w = (const float*)d_in[3];
    const float* wq_b = (const float*)d_in[4];
    const float* wk_w = (const float*)d_in[5];
    const float* wk_b = (const float*)d_in[6];
    const float* wv_w = (const float*)d_in[7];
    const float* wv_b = (const float*)d_in[8];
    const float* wo_w = (const float*)d_in[9];
    const float* wo_b = (const float*)d_in[10];

    void *pXh, *pXl, *pWh, *pWl, *pPh, *pPl, *pOh, *pOl;
    cudaGetSymbolAddress(&pXh, g_Xh);
    cudaGetSymbolAddress(&pXl, g_Xl);
    cudaGetSymbolAddress(&pWh, g_Wh);
    cudaGetSymbolAddress(&pWl, g_Wl);
    cudaGetSymbolAddress(&pPh, g_Ph);
    cudaGetSymbolAddress(&pPl, g_Pl);
    cudaGetSymbolAddress(&pOh, g_Oh);
    cudaGetSymbolAddress(&pOl, g_Ol);

    static int nsm = 0;
    static bool attr_done = false;
    if (!attr_done) {
        cudaFuncSetAttribute(gemm_mma,
                             cudaFuncAttributeMaxDynamicSharedMemorySize, GEMM_SMEM);
        cudaFuncSetAttribute(attn_mma,
                             cudaFuncAttributeMaxDynamicSharedMemorySize, ATTN_SMEM);
        cudaDeviceGetAttribute(&nsm, cudaDevAttrMultiProcessorCount, 0);
        attr_done = true;
    }
    const int pgrid = 2 * nsm;   // persistent: 2 CTAs/SM (smem-bound)

    __nv_bfloat16* Xh = (__nv_bfloat16*)pXh;
    __nv_bfloat16* Xl = (__nv_bfloat16*)pXl;
    __nv_bfloat16* Wh = (__nv_bfloat16*)pWh;
    __nv_bfloat16* Wl = (__nv_bfloat16*)pWl;
    __nv_bfloat16* Ph = (__nv_bfloat16*)pPh;
    __nv_bfloat16* Pl = (__nv_bfloat16*)pPl;

    const int n4x = Mrows * Dd / 4;   // 2,097,152
    const int n4w = Dd * Dd / 4;      // 262,144

    split3_kernel<<<dim3(n4x/256, 3), 256>>>(q, k, v, Xh, Xl, n4x);
    split4_kernel<<<dim3(n4w/256, 4), 256>>>(wq_w, wk_w, wv_w, wo_w, Wh, Wl, n4w);

    // fused persistent Q/K/V projections: 1536 tiles (z in [0,3))
    gemm_mma<<<pgrid, 128, GEMM_SMEM>>>(
        Xh, Xl, Wh, Wl, wq_b, wk_b, wv_b, nullptr, Ph, Pl, 1, 0, 1536);

    attn_mma<<<dim3(Ls/64, Bb*Hh), 128, ATTN_SMEM>>>();

    // persistent output projection: 512 tiles, z = 3
    gemm_mma<<<pgrid, 128, GEMM_SMEM>>>(
        (__nv_bfloat16*)pOh, (__nv_bfloat16*)pOl, Wh, Wl,
        wo_b, wo_b, wo_b, (float*)d_out, nullptr, nullptr, 0, 3, 512);
}

// round 15
// speedup vs baseline: 1.4039x; 1.4039x over previous
#include <cuda_runtime.h>
#include <cuda_bf16.h>
#include <cstdint>

#define Bb 4
#define Ls 2048
#define Dd 1024
#define Hh 16
#define DKk 64
#define Mrows 8192
#define SZ ((size_t)Bb*Hh*Ls*DKk)   // 8,388,608 elements per Q/K/V slab

// ---------------- scratch (__device__ globals; allocation-free rule) -------
__device__ __nv_bfloat16 g_Xh[3*Mrows*Dd];   // split q,k,v inputs (slab z)
__device__ __nv_bfloat16 g_Xl[3*Mrows*Dd];
__device__ __nv_bfloat16 g_Wh[4*Dd*Dd];      // split wq,wk,wv,wo (slab z)
__device__ __nv_bfloat16 g_Wl[4*Dd*Dd];
__device__ __nv_bfloat16 g_Ph[3*Bb*Hh*Ls*DKk];  // Q,K,V hi [B,H,L,DK] slabs
__device__ __nv_bfloat16 g_Pl[3*Bb*Hh*Ls*DKk];
__device__ __nv_bfloat16 g_Oh[Mrows*Dd];     // attn out hi/lo, row-major [M,D]
__device__ __nv_bfloat16 g_Ol[Mrows*Dd];

// ---------------- PTX helpers (family-portable; no tcgen05) ----------------
__device__ __forceinline__ uint32_t s2u(const void* p) {
    uint32_t a;
    asm("{ .reg .u64 t; cvta.to.shared.u64 t, %1; cvt.u32.u64 %0, t; }"
        : "=r"(a) : "l"(p));
    return a;
}
__device__ __forceinline__ void cp16(uint32_t dst, const void* src) {
    asm volatile("cp.async.cg.shared.global [%0], [%1], 16;" :: "r"(dst), "l"(src));
}
__device__ __forceinline__ void ldsm4(uint32_t addr, uint32_t& r0, uint32_t& r1,
                                      uint32_t& r2, uint32_t& r3) {
    asm volatile("ldmatrix.sync.aligned.m8n8.x4.shared.b16 {%0,%1,%2,%3}, [%4];"
                 : "=r"(r0), "=r"(r1), "=r"(r2), "=r"(r3) : "r"(addr));
}
__device__ __forceinline__ void ldsm4t(uint32_t addr, uint32_t& r0, uint32_t& r1,
                                       uint32_t& r2, uint32_t& r3) {
    asm volatile("ldmatrix.sync.aligned.m8n8.x4.trans.shared.b16 {%0,%1,%2,%3}, [%4];"
                 : "=r"(r0), "=r"(r1), "=r"(r2), "=r"(r3) : "r"(addr));
}
__device__ __forceinline__ void mma16816(float* c, const uint32_t* a,
                                         uint32_t b0, uint32_t b1) {
    asm volatile(
        "mma.sync.aligned.m16n8k16.row.col.f32.bf16.bf16.f32 "
        "{%0,%1,%2,%3}, {%4,%5,%6,%7}, {%8,%9}, {%0,%1,%2,%3};"
        : "+f"(c[0]), "+f"(c[1]), "+f"(c[2]), "+f"(c[3])
        : "r"(a[0]), "r"(a[1]), "r"(a[2]), "r"(a[3]), "r"(b0), "r"(b1));
}
__device__ __forceinline__ uint32_t swz(uint32_t off) {
    return off ^ ((off >> 3) & 0x70);
}
__device__ __forceinline__ uint32_t cvt_bf16x2(float h, float l) {
    uint32_t r;
    asm("cvt.rn.bf16x2.f32 %0, %1, %2;" : "=r"(r) : "f"(h), "f"(l));
    return r;
}
// truncation split: hi = x with low 16 mantissa bits zeroed (exact in fp32)
__device__ __forceinline__ uint32_t trunc_bits(float x) {
    return __float_as_uint(x) & 0xffff0000u;
}

// ---------------- batched split kernels: fp32 -> (hi, lo) bf16 --------------
__device__ __forceinline__ void split_store(const float* x, __nv_bfloat16* hi,
                                            __nv_bfloat16* lo, size_t slot)
{
    float4 v = ((const float4*)x)[0];
    float f[4] = {v.x, v.y, v.z, v.w};
    uint32_t ub[4];
    #pragma unroll
    for (int j = 0; j < 4; j++) ub[j] = trunc_bits(f[j]);
    ((uint32_t*)hi)[2*slot]   = __byte_perm(ub[0], ub[1], 0x7632);
    ((uint32_t*)hi)[2*slot+1] = __byte_perm(ub[2], ub[3], 0x7632);
    ((uint32_t*)lo)[2*slot]   = cvt_bf16x2(f[1] - __uint_as_float(ub[1]),
                                           f[0] - __uint_as_float(ub[0]));
    ((uint32_t*)lo)[2*slot+1] = cvt_bf16x2(f[3] - __uint_as_float(ub[3]),
                                           f[2] - __uint_as_float(ub[2]));
}

__global__ __launch_bounds__(256) void split3_kernel(
    const float* __restrict__ x0, const float* __restrict__ x1,
    const float* __restrict__ x2,
    __nv_bfloat16* __restrict__ hi, __nv_bfloat16* __restrict__ lo, int n4)
{
    int i = blockIdx.x * 256 + threadIdx.x;
    if (i >= n4) return;
    int z = blockIdx.y;
    const float* x = (z == 0) ? x0 : (z == 1) ? x1 : x2;
    size_t slot = (size_t)z * n4 + i;
    split_store(x + 4*(size_t)i, hi, lo, slot);
}

__global__ __launch_bounds__(256) void split4_kernel(
    const float* __restrict__ x0, const float* __restrict__ x1,
    const float* __restrict__ x2, const float* __restrict__ x3,
    __nv_bfloat16* __restrict__ hi, __nv_bfloat16* __restrict__ lo, int n4)
{
    int i = blockIdx.x * 256 + threadIdx.x;
    if (i >= n4) return;
    int z = blockIdx.y;
    const float* x = (z == 0) ? x0 : (z == 1) ? x1 : (z == 2) ? x2 : x3;
    size_t slot = (size_t)z * n4 + i;
    split_store(x + 4*(size_t)i, hi, lo, slot);
}

// ---------------- persistent mma.sync bf16x3 GEMM ---------------------------
// Grid-stride over tiles (512 tiles per z-slab: 64 m-blocks x 8 n-blocks).
// scatter=1: bf16 hi/lo out in [B,H,L,DK]; scatter=0: fp32 row-major + bias.
#define GEMM_SMEM 98304   // 3 stages x (A 16KB + B 16KB)

__global__ __launch_bounds__(128) void gemm_mma(
    const __nv_bfloat16* __restrict__ AhB, const __nv_bfloat16* __restrict__ AlB,
    const __nv_bfloat16* __restrict__ WhB, const __nv_bfloat16* __restrict__ WlB,
    const float* __restrict__ b0p, const float* __restrict__ b1p,
    const float* __restrict__ b2p,
    float* __restrict__ C,
    __nv_bfloat16* __restrict__ ChB, __nv_bfloat16* __restrict__ ClB,
    int scatter, int zbase, int ntiles)
{
    extern __shared__ char smem[];
    const uint32_t sb = s2u(smem);
    const int tid = threadIdx.x, wid = tid >> 5, lane = tid & 31;
    const int warp_m = wid & 1, warp_n = wid >> 1;

    const int arow = lane & 15;
    const int akp  = (lane >> 4) & 1;
    const int brow = (lane & 7) + ((lane >> 4) << 3);
    const int bkp  = (lane >> 3) & 1;

    for (int t = blockIdx.x; t < ntiles; t += gridDim.x) {
        const int z = zbase + (t >> 9);
        const int rem = t & 511;
        const int bm = (rem >> 3) * 128, bn = (rem & 7) * 128;
        const int za = scatter ? z : 0;

        const __nv_bfloat16* Ah = AhB + (size_t)za * Mrows * Dd;
        const __nv_bfloat16* Al = AlB + (size_t)za * Mrows * Dd;
        const __nv_bfloat16* Wh = WhB + (size_t)z * Dd * Dd;
        const __nv_bfloat16* Wl = WlB + (size_t)z * Dd * Dd;
        const float* bias = (z == 1) ? b1p : (z == 2) ? b2p : b0p;
        __nv_bfloat16* Ch = ChB + (size_t)z * SZ;
        __nv_bfloat16* Cl = ClB + (size_t)z * SZ;

        float acc[4][8][4] = {};

        auto stage = [&](int c, int buf) {
            const __nv_bfloat16* As = (c >= 16 && c < 32) ? Al : Ah;
            const __nv_bfloat16* Ws = (c < 32) ? Wh : Wl;
            const int koff = (c & 15) << 6;
            const uint32_t abase = sb + buf * 32768;
            const uint32_t bbase = abase + 16384;
            #pragma unroll
            for (int u = 0; u < 8; u++) {
                int i = tid + u * 128;
                int row = i >> 3, seg = i & 7;
                uint32_t off = row * 128 + seg * 16;
                cp16(abase + swz(off), As + (size_t)(bm + row) * Dd + koff + seg * 8);
            }
            #pragma unroll
            for (int u = 0; u < 8; u++) {
                int i = tid + u * 128;
                int row = i >> 3, seg = i & 7;
                uint32_t off = row * 128 + seg * 16;
                cp16(bbase + swz(off), Ws + (size_t)(bn + row) * Dd + koff + seg * 8);
            }
            asm volatile("cp.async.commit_group;" ::: "memory");
        };

        stage(0, 0);
        stage(1, 1);
        for (int c = 0; c < 48; c++) {
            if (c < 46) {
                asm volatile("cp.async.wait_group 1;" ::: "memory");
            } else {
                asm volatile("cp.async.wait_group 0;" ::: "memory");
            }
            __syncthreads();
            if (c + 2 < 48) stage(c + 2, (c + 2) % 3);

            const uint32_t abase = sb + (c % 3) * 32768;
            const uint32_t bbase = abase + 16384;
            #pragma unroll
            for (int ks = 0; ks < 4; ks++) {
                uint32_t a[4][4];
                #pragma unroll
                for (int mt = 0; mt < 4; mt++) {
                    int r = warp_m * 64 + mt * 16 + arow;
                    ldsm4(abase + swz(r * 128 + ks * 32 + akp * 16),
                          a[mt][0], a[mt][1], a[mt][2], a[mt][3]);
                }
                uint32_t b[4][4];
                #pragma unroll
                for (int nt2 = 0; nt2 < 4; nt2++) {
                    int r = warp_n * 64 + nt2 * 16 + brow;
                    ldsm4(bbase + swz(r * 128 + ks * 32 + bkp * 16),
                          b[nt2][0], b[nt2][1], b[nt2][2], b[nt2][3]);
                }
                #pragma unroll
                for (int mt = 0; mt < 4; mt++)
                    #pragma unroll
                    for (int nt2 = 0; nt2 < 4; nt2++) {
                        mma16816(acc[mt][nt2*2],     a[mt], b[nt2][0], b[nt2][1]);
                        mma16816(acc[mt][nt2*2 + 1], a[mt], b[nt2][2], b[nt2][3]);
                    }
            }
        }

        #pragma unroll
        for (int mt = 0; mt < 4; mt++) {
            int row0 = bm + warp_m * 64 + mt * 16 + (lane >> 2);
            #pragma unroll
            for (int nt = 0; nt < 8; nt++) {
                int col = bn + warp_n * 64 + nt * 8 + (lane & 3) * 2;
                float c0 = __ldg(bias + col), c1 = __ldg(bias + col + 1);
                #pragma unroll
                for (int half = 0; half < 2; half++) {
                    int m = row0 + half * 8;
                    float v0 = acc[mt][nt][half*2]     + c0;
                    float v1 = acc[mt][nt][half*2 + 1] + c1;
                    if (scatter) {
                        int b_ = m >> 11, l_ = m & 2047;
                        int h_ = col >> 6, d_ = col & 63;
                        size_t idx = ((size_t)((b_ * Hh + h_) * Ls + l_)) * DKk + d_;
                        uint32_t u0 = trunc_bits(v0), u1 = trunc_bits(v1);
                        *(uint32_t*)(Ch + idx) = __byte_perm(u0, u1, 0x7632);
                        *(uint32_t*)(Cl + idx) =
                            cvt_bf16x2(v1 - __uint_as_float(u1),
                                       v0 - __uint_as_float(u0));
                    } else {
                        float2 v; v.x = v0; v.y = v1;
                        *(float2*)(C + (size_t)m * Dd + col) = v;
                    }
                }
            }
        }
    }
}

// ---------------- tensor-core flash attention (bf16x3, FA2-style) -----------
// Byte-identical to R11 (the 839.8us best): serves as clock canary this round.
// CTA: 64 queries x one (b,h). 4 warps x 16 rows. 3 CTAs/SM.
#define ATTN_SMEM 65536
#define C8 0.18033688011112042f   // 0.125 * log2(e)

__global__ __launch_bounds__(128, 3) void attn_mma()
{
    extern __shared__ char smem[];
    const uint32_t sb = s2u(smem);
    const int tid = threadIdx.x, wid = tid >> 5, lane = tid & 31;
    const int qt = (int)gridDim.x - 1 - (int)blockIdx.x;   // long CTAs first
    const int bh = blockIdx.y;
    const size_t hb = (size_t)bh * Ls * DKk;
    const __nv_bfloat16* Qh_g = g_Ph + hb;
    const __nv_bfloat16* Ql_g = g_Pl + hb;
    const __nv_bfloat16* srcs[4] = {g_Ph + SZ + hb, g_Pl + SZ + hb,
                                    g_Ph + 2*SZ + hb, g_Pl + 2*SZ + hb};

    const int arow = lane & 15;
    const int akp  = (lane >> 4) & 1;
    const int brow = (lane & 7) + ((lane >> 4) << 3);
    const int bkp  = (lane >> 3) & 1;
    const int vrow = (lane & 7) + (((lane >> 3) & 1) << 3);
    const int vdb  = (lane >> 4) * 16;

    // stage Q hi/lo into ring buffer 0 (Kh/Kl slots), then KV tile 0 -> buf 1
    {
        #pragma unroll
        for (int u = 0; u < 4; u++) {
            int i = tid + u * 128;
            int row = i >> 3, seg = i & 7;
            uint32_t off = swz(row * 128 + seg * 16);
            cp16(sb + off,        Qh_g + (size_t)(qt*64 + row) * DKk + seg * 8);
            cp16(sb + 8192 + off, Ql_g + (size_t)(qt*64 + row) * DKk + seg * 8);
        }
        asm volatile("cp.async.commit_group;" ::: "memory");
    }
    auto stage_kv = [&](int kt2, int buf) {
        const uint32_t base = sb + buf * 32768;
        #pragma unroll
        for (int tile = 0; tile < 4; tile++) {
            const __nv_bfloat16* sp = srcs[tile] + (size_t)(kt2 * 64) * DKk;
            uint32_t db = base + tile * 8192;
            #pragma unroll
            for (int u = 0; u < 4; u++) {
                int i = tid + u * 128;
                int row = i >> 3, seg = i & 7;
                cp16(db + swz(row * 128 + seg * 16), sp + row * DKk + seg * 8);
            }
        }
        asm volatile("cp.async.commit_group;" ::: "memory");
    };
    stage_kv(0, 1);

    // Q fragments -> registers (per-thread wait, then CTA-wide sync: cp.async
    // groups are per-thread; ldmatrix reads other threads' staged bytes)
    uint32_t qh[4][4], ql[4][4];
    asm volatile("cp.async.wait_group 1;" ::: "memory");
    __syncthreads();
    #pragma unroll
    for (int ks = 0; ks < 4; ks++) {
        uint32_t off = swz((wid*16 + arow) * 128 + ks * 32 + akp * 16);
        ldsm4(sb + off,        qh[ks][0], qh[ks][1], qh[ks][2], qh[ks][3]);
        ldsm4(sb + 8192 + off, ql[ks][0], ql[ks][1], ql[ks][2], ql[ks][3]);
    }
    __syncthreads();   // all warps done reading Q region; buf0 reusable

    float o[8][4] = {};
    float m_a = -1e30f, m_b = -1e30f, l_a = 0.f, l_b = 0.f;
    const int rA = wid * 16 + (lane >> 2);
    const int cL = (lane & 3) * 2;

    for (int kt = 0; kt <= qt; kt++) {
        const int cur = (kt & 1) ^ 1;          // kt0->buf1, kt1->buf0, ...
        if (kt < qt) {
            stage_kv(kt + 1, cur ^ 1);
            asm volatile("cp.async.wait_group 1;" ::: "memory");
        } else {
            asm volatile("cp.async.wait_group 0;" ::: "memory");
        }
        __syncthreads();

        const uint32_t kb  = sb + cur * 32768;
        const uint32_t klb = kb + 8192;
        const uint32_t vb  = kb + 16384;
        const uint32_t vlb = kb + 24576;

        // ---- S = Q K^T (bf16x3; scale folded into exp2) ----
        float s[8][4] = {};
        #pragma unroll
        for (int ks = 0; ks < 4; ks++) {
            uint32_t bk[4][4];
            #pragma unroll
            for (int p = 0; p < 4; p++)
                ldsm4(kb + swz((p*16 + brow) * 128 + ks * 32 + bkp * 16),
                      bk[p][0], bk[p][1], bk[p][2], bk[p][3]);
            #pragma unroll
            for (int p = 0; p < 4; p++) {
                mma16816(s[2*p],   qh[ks], bk[p][0], bk[p][1]);
                mma16816(s[2*p+1], qh[ks], bk[p][2], bk[p][3]);
                mma16816(s[2*p],   ql[ks], bk[p][0], bk[p][1]);
                mma16816(s[2*p+1], ql[ks], bk[p][2], bk[p][3]);
            }
            #pragma unroll
            for (int p = 0; p < 4; p++) {
                ldsm4(klb + swz((p*16 + brow) * 128 + ks * 32 + bkp * 16),
                      bk[p][0], bk[p][1], bk[p][2], bk[p][3]);
                mma16816(s[2*p],   qh[ks], bk[p][0], bk[p][1]);
                mma16816(s[2*p+1], qh[ks], bk[p][2], bk[p][3]);
            }
        }

        if (kt == qt) {   // causal mask within diagonal tile (raw domain)
            #pragma unroll
            for (int t = 0; t < 8; t++) {
                int c = t * 8 + cL;
                if (c     > rA)     s[t][0] = -1e30f;
                if (c + 1 > rA)     s[t][1] = -1e30f;
                if (c     > rA + 8) s[t][2] = -1e30f;
                if (c + 1 > rA + 8) s[t][3] = -1e30f;
            }
        }

        // ---- online softmax: exp((s-nm)/8) = exp2(fma(s, C8, -nm*C8)) ----
        float tmA = -1e30f, tmB = -1e30f;
        #pragma unroll
        for (int t = 0; t < 8; t++) {
            tmA = fmaxf(tmA, fmaxf(s[t][0], s[t][1]));
            tmB = fmaxf(tmB, fmaxf(s[t][2], s[t][3]));
        }
        tmA = fmaxf(tmA, __shfl_xor_sync(0xffffffffu, tmA, 1));
        tmA = fmaxf(tmA, __shfl_xor_sync(0xffffffffu, tmA, 2));
        tmB = fmaxf(tmB, __shfl_xor_sync(0xffffffffu, tmB, 1));
        tmB = fmaxf(tmB, __shfl_xor_sync(0xffffffffu, tmB, 2));
        float nmA = fmaxf(m_a, tmA), nmB = fmaxf(m_b, tmB);
        float alA = exp2f((m_a - nmA) * C8), alB = exp2f((m_b - nmB) * C8);
        m_a = nmA; m_b = nmB;
        float nAc = nmA * C8, nBc = nmB * C8;

        float psA = 0.f, psB = 0.f;
        #pragma unroll
        for (int t = 0; t < 8; t++) {
            s[t][0] = exp2f(fmaf(s[t][0], C8, -nAc));
            s[t][1] = exp2f(fmaf(s[t][1], C8, -nAc));
            s[t][2] = exp2f(fmaf(s[t][2], C8, -nBc));
            s[t][3] = exp2f(fmaf(s[t][3], C8, -nBc));
            psA += s[t][0] + s[t][1];
            psB += s[t][2] + s[t][3];
        }
        l_a = l_a * alA + psA;
        l_b = l_b * alB + psB;
        #pragma unroll
        for (int t = 0; t < 8; t++) {
            o[t][0] *= alA; o[t][1] *= alA;
            o[t][2] *= alB; o[t][3] *= alB;
        }

        // ---- P hi/lo via truncation split (PRMT + bf16x2 cvt) ----
        uint32_t aph[4][4], apl[4][4];
        #pragma unroll
        for (int kc = 0; kc < 4; kc++) {
            #pragma unroll
            for (int half = 0; half < 2; half++) {
                int t = 2*kc + half;
                uint32_t xb = trunc_bits(s[t][0]), yb = trunc_bits(s[t][1]);
                uint32_t zb = trunc_bits(s[t][2]), wb = trunc_bits(s[t][3]);
                aph[kc][half*2]   = __byte_perm(xb, yb, 0x7632);
                aph[kc][half*2+1] = __byte_perm(zb, wb, 0x7632);
                apl[kc][half*2]   = cvt_bf16x2(s[t][1] - __uint_as_float(yb),
                                               s[t][0] - __uint_as_float(xb));
                apl[kc][half*2+1] = cvt_bf16x2(s[t][3] - __uint_as_float(wb),
                                               s[t][2] - __uint_as_float(zb));
            }
        }

        // ---- O += P V (3 bf16 passes); V via ldmatrix.trans ----
        #pragma unroll
        for (int kc = 0; kc < 4; kc++) {
            uint32_t bv[4][4];
            #pragma unroll
            for (int p = 0; p < 4; p++)
                ldsm4t(vb + swz((kc*16 + vrow) * 128 + p * 32 + vdb),
                       bv[p][0], bv[p][1], bv[p][2], bv[p][3]);
            #pragma unroll
            for (int p = 0; p < 4; p++) {
                mma16816(o[2*p],   aph[kc], bv[p][0], bv[p][1]);
                mma16816(o[2*p+1], aph[kc], bv[p][2], bv[p][3]);
                mma16816(o[2*p],   apl[kc], bv[p][0], bv[p][1]);
                mma16816(o[2*p+1], apl[kc], bv[p][2], bv[p][3]);
            }
            #pragma unroll
            for (int p = 0; p < 4; p++) {
                ldsm4t(vlb + swz((kc*16 + vrow) * 128 + p * 32 + vdb),
                       bv[p][0], bv[p][1], bv[p][2], bv[p][3]);
                mma16816(o[2*p],   aph[kc], bv[p][0], bv[p][1]);
                mma16816(o[2*p+1], aph[kc], bv[p][2], bv[p][3]);
            }
        }
        __syncthreads();
    }

    l_a += __shfl_xor_sync(0xffffffffu, l_a, 1);
    l_a += __shfl_xor_sync(0xffffffffu, l_a, 2);
    l_b += __shfl_xor_sync(0xffffffffu, l_b, 1);
    l_b += __shfl_xor_sync(0xffffffffu, l_b, 2);
    float invA = 1.f / l_a, invB = 1.f / l_b;
    const int b_ = bh >> 4, h_ = bh & 15;
    const int rowA = qt * 64 + rA;
    #pragma unroll
    for (int t = 0; t < 8; t++) {
        int d0 = h_ * 64 + t * 8 + cL;
        float a0 = o[t][0] * invA, a1 = o[t][1] * invA;
        float b0 = o[t][2] * invB, b1 = o[t][3] * invB;
        size_t iA = ((size_t)(b_ * Ls + rowA))     * Dd + d0;
        size_t iB = ((size_t)(b_ * Ls + rowA + 8)) * Dd + d0;
        uint32_t ua0 = trunc_bits(a0), ua1 = trunc_bits(a1);
        uint32_t ub0 = trunc_bits(b0), ub1 = trunc_bits(b1);
        *(uint32_t*)(g_Oh + iA) = __byte_perm(ua0, ua1, 0x7632);
        *(uint32_t*)(g_Ol + iA) = cvt_bf16x2(a1 - __uint_as_float(ua1),
                                             a0 - __uint_as_float(ua0));
        *(uint32_t*)(g_Oh + iB) = __byte_perm(ub0, ub1, 0x7632);
        *(uint32_t*)(g_Ol + iB) = cvt_bf16x2(b1 - __uint_as_float(ub1),
                                             b0 - __uint_as_float(ub0));
    }
}

// ---------------- launch -----------------------------------------------------
extern "C" void kernel_launch(void* const* d_in, const int* in_sizes, int n_in,
                              void* d_out, int out_size)
{
    const float* q    = (const float*)d_in[0];
    const float* k    = (const float*)d_in[1];
    const float* v    = (const float*)d_in[2];
    const float* wq_w = (const float*)d_in[3];
    const float* wq_b = (const float*)d_in[4];
    const float* wk_w = (const float*)d_in[5];
    const float* wk_b = (const float*)d_in[6];
    const float* wv_w = (const float*)d_in[7];
    const float* wv_b = (const float*)d_in[8];
    const float* wo_w = (const float*)d_in[9];
    const float* wo_b = (const float*)d_in[10];

    void *pXh, *pXl, *pWh, *pWl, *pPh, *pPl, *pOh, *pOl;
    cudaGetSymbolAddress(&pXh, g_Xh);
    cudaGetSymbolAddress(&pXl, g_Xl);
    cudaGetSymbolAddress(&pWh, g_Wh);
    cudaGetSymbolAddress(&pWl, g_Wl);
    cudaGetSymbolAddress(&pPh, g_Ph);
    cudaGetSymbolAddress(&pPl, g_Pl);
    cudaGetSymbolAddress(&pOh, g_Oh);
    cudaGetSymbolAddress(&pOl, g_Ol);

    static int nsm = 0;
    static bool attr_done = false;
    if (!attr_done) {
        cudaFuncSetAttribute(gemm_mma,
                             cudaFuncAttributeMaxDynamicSharedMemorySize, GEMM_SMEM);
        cudaFuncSetAttribute(attn_mma,
                             cudaFuncAttributeMaxDynamicSharedMemorySize, ATTN_SMEM);
        cudaDeviceGetAttribute(&nsm, cudaDevAttrMultiProcessorCount, 0);
        attr_done = true;
    }
    const int pgrid = 2 * nsm;   // persistent: 2 CTAs/SM (smem-bound)

    __nv_bfloat16* Xh = (__nv_bfloat16*)pXh;
    __nv_bfloat16* Xl = (__nv_bfloat16*)pXl;
    __nv_bfloat16* Wh = (__nv_bfloat16*)pWh;
    __nv_bfloat16* Wl = (__nv_bfloat16*)pWl;
    __nv_bfloat16* Ph = (__nv_bfloat16*)pPh;
    __nv_bfloat16* Pl = (__nv_bfloat16*)pPl;

    const int n4x = Mrows * Dd / 4;   // 2,097,152
    const int n4w = Dd * Dd / 4;      // 262,144

    split3_kernel<<<dim3(n4x/256, 3), 256>>>(q, k, v, Xh, Xl, n4x);
    split4_kernel<<<dim3(n4w/256, 4), 256>>>(wq_w, wk_w, wv_w, wo_w, Wh, Wl, n4w);

    // fused persistent Q/K/V projections: 1536 tiles (z in [0,3))
    gemm_mma<<<pgrid, 128, GEMM_SMEM>>>(
        Xh, Xl, Wh, Wl, wq_b, wk_b, wv_b, nullptr, Ph, Pl, 1, 0, 1536);

    attn_mma<<<dim3(Ls/64, Bb*Hh), 128, ATTN_SMEM>>>();

    // persistent output projection: 512 tiles, z = 3
    gemm_mma<<<pgrid, 128, GEMM_SMEM>>>(
        (__nv_bfloat16*)pOh, (__nv_bfloat16*)pOl, Wh, Wl,
        wo_b, wo_b, wo_b, (float*)d_out, nullptr, nullptr, 0, 3, 512);
}